// round 15
// baseline (speedup 1.0000x reference)
#include <cuda_runtime.h>
#include <cuda_fp16.h>
#include <cstdint>
#include <math.h>

// ---------------------------------------------------------------- constants
#define B_     16
#define IC_    512
#define OC_    512
#define HW_    32
#define STYLE_ 512
#define AFF_SCALE 0.04419417382415922f   // 1/sqrt(512)
#define W_SCALE   0.014731391274719739f  // 1/sqrt(512*9)

// ---------------------------------------------------------------- scratch
__device__ float g_s   [B_ * IC_];
__device__ float g_cw2t[IC_ * OC_];
__device__ float g_d   [B_ * OC_];
// padded x plane: [b 16][chunk 8][1156 rows][64 ic] halves, swizzled rows.
// row q = (h+1)*34 + (w+1), h,w in [-1,32]; pad rows/cols never written -> zero.
#define XROWS 1156
__device__ __half g_x2 [B_ * 8 * XROWS * 64];
// weights: [(tap*8+chunk)*4+ocb] tiles of [128 row][64 ic] halves, swizzled.
__device__ __half g_wk2[9 * 8 * 4 * 128 * 64];

// ---------------------------------------------------------------- utils
__device__ __forceinline__ uint32_t smem_u32(const void* p) {
    uint32_t a;
    asm("{ .reg .u64 t; cvta.to.shared.u64 t, %1; cvt.u32.u64 %0, t; }" : "=r"(a) : "l"(p));
    return a;
}
#define LDSM_X4(r0, r1, r2, r3, addr) \
    asm volatile("ldmatrix.sync.aligned.m8n8.x4.shared.b16 {%0,%1,%2,%3}, [%4];" \
                 : "=r"(r0), "=r"(r1), "=r"(r2), "=r"(r3) : "r"(addr))
#define MBAR_INIT(a, c) asm volatile("mbarrier.init.shared.b64 [%0], %1;" :: "r"(a), "r"(c) : "memory")
#define MBAR_EXPECT(a, tx) \
    asm volatile("mbarrier.arrive.expect_tx.shared.b64 _, [%0], %1;" :: "r"(a), "r"(tx) : "memory")
#define BULK_G2S(dst, src, sz, mbar) \
    asm volatile("cp.async.bulk.shared::cluster.global.mbarrier::complete_tx::bytes [%0], [%1], %2, [%3];" \
                 :: "r"(dst), "l"(src), "r"(sz), "r"(mbar) : "memory")
__device__ __forceinline__ void mbar_wait(uint32_t addr, uint32_t parity) {
    asm volatile(
        "{\n\t.reg .pred P;\n\t"
        "W_%=:\n\t"
        "mbarrier.try_wait.parity.shared.b64 P, [%0], %1;\n\t"
        "@P bra.uni D_%=;\n\t"
        "bra.uni W_%=;\n\t"
        "D_%=:\n\t}"
        :: "r"(addr), "r"(parity) : "memory");
}

// ---------------------------------------------------------------- prep kernels
// wsq + output zeroing fused. grid 1024 x 256.
__global__ void wsq_zero_kernel(const float* __restrict__ cw, float4* __restrict__ out4) {
    int idx = blockIdx.x * blockDim.x + threadIdx.x;
    if (idx < OC_ * IC_) {
        int o = idx / IC_, i = idx - o * IC_;
        const float* p = cw + (size_t)idx * 9;
        float a = 0.f;
        #pragma unroll
        for (int k = 0; k < 9; k++) a = fmaf(p[k], p[k], a);
        g_cw2t[i * OC_ + o] = a;
    }
    const float4 z = make_float4(0.f, 0.f, 0.f, 0.f);
    #pragma unroll
    for (int e = 0; e < 8; e++)
        out4[e * 262144 + idx] = z;
}

// affine + demod fused: block b, 512 threads.
__global__ void affine_demod_kernel(const float* __restrict__ style,
                                    const float* __restrict__ aff_w,
                                    const float* __restrict__ aff_b) {
    int b = blockIdx.x, i = threadIdx.x;
    __shared__ float st[STYLE_];
    __shared__ float s2[IC_];
    st[i] = style[b * STYLE_ + i];
    __syncthreads();
    const float* wrow = aff_w + (size_t)i * STYLE_;
    float acc = 0.f;
    #pragma unroll 8
    for (int j = 0; j < STYLE_; j++) acc = fmaf(wrow[j], st[j], acc);
    float sp = (acc * AFF_SCALE + aff_b[i] + 1.0f) * W_SCALE;
    g_s[b * IC_ + i] = sp;
    s2[i] = sp * sp;
    __syncthreads();
    float a = 0.f;
    #pragma unroll 8
    for (int k = 0; k < IC_; k++) a = fmaf(s2[k], g_cw2t[k * OC_ + i], a);
    g_d[b * OC_ + i] = rsqrtf(a + 1e-8f);
}

// Build the padded x plane: style-scaled, half, transposed, swizzled.
__global__ void build_x2_kernel(const float* __restrict__ x) {
    __shared__ float t[64][133];
    const int b     = blockIdx.x >> 3;
    const int chunk = blockIdx.x & 7;
    const int ic0   = chunk * 64;
    const int hq    = blockIdx.y;
    const int tid   = threadIdx.x;

    #pragma unroll
    for (int e = 0; e < 8; e++) {
        int idx = e * 256 + tid;
        int ic = idx >> 5, p4 = idx & 31;
        float4 v = *(const float4*)(x + ((size_t)(b * IC_ + ic0 + ic)) * 1024 + hq * 128 + p4 * 4);
        float s = g_s[b * IC_ + ic0 + ic];
        t[ic][p4 * 4 + 0] = v.x * s;
        t[ic][p4 * 4 + 1] = v.y * s;
        t[ic][p4 * 4 + 2] = v.z * s;
        t[ic][p4 * 4 + 3] = v.w * s;
    }
    __syncthreads();

    #pragma unroll
    for (int e = 0; e < 4; e++) {
        int idx = e * 256 + tid;
        int r = idx >> 3, c = idx & 7;
        uint32_t u[4];
        #pragma unroll
        for (int jj = 0; jj < 4; jj++) {
            __half2 hv = __floats2half2_rn(t[8 * c + 2 * jj][r], t[8 * c + 2 * jj + 1][r]);
            u[jj] = *(uint32_t*)&hv;
        }
        const int h = hq * 4 + (r >> 5), w = r & 31;
        const int q = (h + 1) * 34 + (w + 1);
        size_t base = (((size_t)b * 8 + chunk) * XROWS + q) * 64;
        uint4* dst = (uint4*)(g_x2 + base + ((c ^ (q & 7)) * 8));
        *dst = make_uint4(u[0], u[1], u[2], u[3]);
    }
}

// Coalesced weight repack: 256 blocks = (chunk 8, ocb 4, rowgroup 8), 16 rows each.
__global__ void build_w2_kernel(const float* __restrict__ cw) {
    __shared__ float ws[16 * 576];
    const int bx    = blockIdx.x;
    const int rg    = bx & 7;
    const int ocb   = (bx >> 3) & 3;
    const int chunk = bx >> 5;
    const int tid   = threadIdx.x;
    const int o0    = ocb * 128 + rg * 16;
    const int ic0   = chunk * 64;

    #pragma unroll
    for (int t = 0; t < 36; t++) {
        int idx = t * 256 + tid;
        int row = idx / 576, col = idx - row * 576;
        ws[idx] = cw[((size_t)(o0 + row) * IC_ + ic0) * 9 + col];
    }
    __syncthreads();

    #pragma unroll
    for (int e = 0; e < 5; e++) {
        int idx = e * 256 + tid;
        if (idx < 1152) {                      // lr*72 + tap*8 + c
            int c   = idx & 7;
            int tap = (idx >> 3) % 9;
            int lr  = idx / 72;
            uint32_t u[4];
            #pragma unroll
            for (int jj = 0; jj < 4; jj++) {
                float f0 = ws[lr * 576 + (8 * c + 2 * jj) * 9 + tap];
                float f1 = ws[lr * 576 + (8 * c + 2 * jj + 1) * 9 + tap];
                __half2 hv = __floats2half2_rn(f0, f1);
                u[jj] = *(uint32_t*)&hv;
            }
            int row = rg * 16 + lr;
            uint4* dst = (uint4*)(g_wk2 + (size_t)((tap * 8 + chunk) * 4 + ocb) * 8192
                                  + row * 64 + ((c ^ (row & 7)) * 8));
            *dst = make_uint4(u[0], u[1], u[2], u[3]);
        }
    }
}

// ---------------------------------------------------------------- stream-K fp16 mma conv
// CTA tile 256x128, 256 threads (8 warps 4Mx2N, warp 64x64), 1 CTA/SM.
// 256 tiles (2 ocb2 x 16 b x 8 hq) x 72 k-units over 148 persistent CTAs.
// Slot mapping: unit u -> slot (u & 1) EVERYWHERE, including the prologue.
#define A_B    32768
#define TILE_B 16384
#define STG_B  (A_B + TILE_B)        // 49152
#define MB_OFF (2 * STG_B)           // 98304
#define SMEM_CONV (MB_OFF + 64)
#define NTILES 256
#define KITERS 72
#define TOTUNITS (NTILES * KITERS)   // 18432
#define NCTA 148

__global__ __launch_bounds__(256, 1)
void conv_mma(float* __restrict__ out) {
    extern __shared__ char smc[];
    const uint32_t sb = smem_u32(smc);
    const int tid = threadIdx.x;
    const int wid = tid >> 5, lane = tid & 31;
    const int g = lane >> 2, tg = lane & 3;
    const int m_w = (wid >> 1) * 64;       // 0,64,128,192
    const int n_w = (wid & 1) * 64;        // 0,64

    const int r7   = lane & 7;
    const int aRow = m_w + ((lane >> 3) & 1) * 8 + r7;
    const int aHi  = lane >> 4;
    const int bRow = n_w + ((lane >> 4) ? 8 : 0) + r7;
    const int bHi  = (lane >> 3) & 1;

    const int bid = blockIdx.x;
    const int u0 = (int)(((long long)bid * TOTUNITS) / NCTA);
    const int u1 = (int)(((long long)(bid + 1) * TOTUNITS) / NCTA);

    if (tid == 0) {
        MBAR_INIT(sb + MB_OFF + 0, 1);
        MBAR_INIT(sb + MB_OFF + 8, 1);
    }
    __syncthreads();

    float acc[4][8][4];
    #pragma unroll
    for (int mi = 0; mi < 4; mi++)
        #pragma unroll
        for (int ni = 0; ni < 8; ni++)
            #pragma unroll
            for (int c = 0; c < 4; c++) acc[mi][ni][c] = 0.f;

    auto issue = [&](int u, int s) {
        const int tile = u / KITERS;
        const int kit  = u - tile * KITERS;
        const int tap = kit % 9, chunk = kit / 9;
        const int dh = tap / 3 - 1, dw = tap % 3 - 1;
        const int ocb2 = tile >> 7;
        const int by   = tile & 127;
        const int bb   = by >> 3;
        const int h0   = (by & 7) * 4;
        const uint32_t mb = sb + MB_OFF + s * 8;
        MBAR_EXPECT(mb, (uint32_t)STG_B);
        const __half* asrc = g_wk2 + (size_t)((tap * 8 + chunk) * 4 + ocb2 * 2) * 8192;
        BULK_G2S(sb + s * STG_B, asrc, A_B, mb);
        const __half* bplane = g_x2 + ((size_t)bb * 8 + chunk) * (XROWS * 64);
        #pragma unroll
        for (int pr = 0; pr < 4; pr++) {
            const int q = (h0 + dh + pr + 1) * 34 + (dw + 1);
            BULK_G2S(sb + s * STG_B + A_B + pr * 4096, bplane + (size_t)q * 64, 4096, mb);
        }
    };

    auto flush = [&](int tile) {
        const int ocbase = (tile >> 7) * 256;
        const int by = tile & 127;
        const int bb = by >> 3;
        const int h0 = (by & 7) * 4;
        #pragma unroll
        for (int mi = 0; mi < 4; mi++) {
            const int r0 = m_w + mi * 16 + g;
            const float d0 = g_d[bb * OC_ + ocbase + r0];
            const float d1 = g_d[bb * OC_ + ocbase + r0 + 8];
            #pragma unroll
            for (int ni = 0; ni < 8; ni++) {
                const int col = n_w + ni * 8 + 2 * tg;
                const int h = h0 + (col >> 5), w = col & 31;
                float* p0 = out + (((size_t)(bb * OC_ + ocbase + r0)) * 32 + h) * 32 + w;
                float* p1 = out + (((size_t)(bb * OC_ + ocbase + r0 + 8)) * 32 + h) * 32 + w;
                atomicAdd(p0,     acc[mi][ni][0] * d0);
                atomicAdd(p0 + 1, acc[mi][ni][1] * d0);
                atomicAdd(p1,     acc[mi][ni][2] * d1);
                atomicAdd(p1 + 1, acc[mi][ni][3] * d1);
                acc[mi][ni][0] = acc[mi][ni][1] = acc[mi][ni][2] = acc[mi][ni][3] = 0.f;
            }
        }
    };

    if (tid == 0) {
        issue(u0, u0 & 1);                         // FIX: slot keyed to unit parity
        if (u0 + 1 < u1) issue(u0 + 1, (u0 + 1) & 1);
    }

    uint32_t phs[2] = {0, 0};
    int cur_tile = u0 / KITERS;

    #pragma unroll 1
    for (int u = u0; u < u1; u++) {
        const int s = u & 1;
        const int tile = u / KITERS;
        if (tile != cur_tile) { flush(cur_tile); cur_tile = tile; }

        mbar_wait(sb + MB_OFF + s * 8, phs[s]);
        phs[s] ^= 1;

        const uint32_t Ab = sb + s * STG_B;
        const uint32_t Bb = Ab + A_B;

        const int kit = u - tile * KITERS;
        const int tap = kit % 9;
        const int dh  = tap / 3 - 1, dwc = tap % 3 - 1;
        const int h0  = ((tile & 127) & 7) * 4;
        const int kbase = (2 * (h0 + dh + 1) + dwc + 1) & 7;

        uint32_t bAdr[4]; int bKey[4];
        #pragma unroll
        for (int nj = 0; nj < 4; nj++) {
            const int rowp = bRow + nj * 16;
            bAdr[nj] = Bb + (uint32_t)rowp * 128;
            bKey[nj] = (kbase + 2 * (rowp >> 5) + r7) & 7;
        }

        // register-stage double-buffered fragment pipeline
        uint32_t af[2][4][4], bf[2][4][4];
        {
            const int cA = aHi ^ r7;
            #pragma unroll
            for (int mi = 0; mi < 4; mi++)
                LDSM_X4(af[0][mi][0], af[0][mi][1], af[0][mi][2], af[0][mi][3],
                        Ab + (uint32_t)(aRow + mi * 16) * 128 + cA * 16);
            #pragma unroll
            for (int nj = 0; nj < 4; nj++)
                LDSM_X4(bf[0][nj][0], bf[0][nj][1], bf[0][nj][2], bf[0][nj][3],
                        bAdr[nj] + ((bHi ^ bKey[nj]) * 16));
        }
        #pragma unroll
        for (int ks = 0; ks < 4; ks++) {
            const int cb = ks & 1;
            if (ks < 3) {
                const int nb = cb ^ 1;
                const int cA = (2 * (ks + 1) + aHi) ^ r7;
                #pragma unroll
                for (int mi = 0; mi < 4; mi++)
                    LDSM_X4(af[nb][mi][0], af[nb][mi][1], af[nb][mi][2], af[nb][mi][3],
                            Ab + (uint32_t)(aRow + mi * 16) * 128 + cA * 16);
                #pragma unroll
                for (int nj = 0; nj < 4; nj++)
                    LDSM_X4(bf[nb][nj][0], bf[nb][nj][1], bf[nb][nj][2], bf[nb][nj][3],
                            bAdr[nj] + (((2 * (ks + 1) + bHi) ^ bKey[nj]) * 16));
            }
            #pragma unroll
            for (int mi = 0; mi < 4; mi++)
                #pragma unroll
                for (int ni = 0; ni < 8; ni++) {
                    const uint32_t b0 = bf[cb][ni >> 1][(ni & 1) * 2];
                    const uint32_t b1 = bf[cb][ni >> 1][(ni & 1) * 2 + 1];
                    asm volatile(
                        "mma.sync.aligned.m16n8k16.row.col.f32.f16.f16.f32 "
                        "{%0,%1,%2,%3}, {%4,%5,%6,%7}, {%8,%9}, {%0,%1,%2,%3};"
                        : "+f"(acc[mi][ni][0]), "+f"(acc[mi][ni][1]),
                          "+f"(acc[mi][ni][2]), "+f"(acc[mi][ni][3])
                        : "r"(af[cb][mi][0]), "r"(af[cb][mi][1]),
                          "r"(af[cb][mi][2]), "r"(af[cb][mi][3]),
                          "r"(b0), "r"(b1));
                }
        }

        __syncthreads();                       // all warps done with slot s
        if (tid == 0 && u + 2 < u1) issue(u + 2, s);
    }

    flush(cur_tile);
}

// ---------------------------------------------------------------- launch
extern "C" void kernel_launch(void* const* d_in, const int* in_sizes, int n_in,
                              void* d_out, int out_size) {
    const float* x    = (const float*)d_in[0];
    const float* sty  = (const float*)d_in[1];
    const float* affw = (const float*)d_in[2];
    const float* affb = (const float*)d_in[3];
    const float* cw   = (const float*)d_in[4];
    float* out = (float*)d_out;

    wsq_zero_kernel<<<1024, 256>>>(cw, (float4*)out);
    affine_demod_kernel<<<B_, 512>>>(sty, affw, affb);
    {
        dim3 g(B_ * 8, 8);
        build_x2_kernel<<<g, 256>>>(x);
    }
    build_w2_kernel<<<256, 256>>>(cw);

    cudaFuncSetAttribute(conv_mma, cudaFuncAttributeMaxDynamicSharedMemorySize, SMEM_CONV);
    conv_mma<<<NCTA, 256, SMEM_CONV>>>(out);
}